// round 15
// baseline (speedup 1.0000x reference)
#include <cuda_runtime.h>
#include <cuda_bf16.h>
#include <cstdint>

#define FULLM 0xFFFFFFFFu

// Problem dims
#define DD 128
#define KK 1024
#define M_TOTAL 32768

// GEMM tiling
#define BM 64
#define BN 128
#define STR 136            // padded bf16 row stride (272B) for A/B tiles
#define NCHUNK (KK/BN)     // 8
#define NTHREADS 256       // 8 warps: 4 (M) x 2 (N), warptile 16x64

// scores staging tile: 64 rows x 136 floats (stride-136 -> conflict-free)
#define SSTR 136
#define STAGE_BYTES (BM*SSTR*4)         // 34816

// smem layout (bytes)
#define A_OFF    0
#define A_BYTES  STAGE_BYTES            // A bf16 tile (17408) lives inside stage area
#define B_OFF    A_BYTES                // ring of 2
#define B_HALF   (BN*STR*2)             // 34816
#define NPSQ_OFF (B_OFF + 2*B_HALF)     // 104448
#define XSQ_OFF  (NPSQ_OFF + 4096)      // 108544
#define MBAR_OFF (XSQ_OFF + 256)        // 108800
#define SMEM_BYTES (MBAR_OFF + 64)      // 108864 (x2 CTAs = 217728 <= 227KB)

// device scratch: P tiles pre-laid-out as padded [128][STR] bf16 smem images
__device__ __align__(16) unsigned char g_pimg[NCHUNK*B_HALF];
__device__ float g_psq[KK];
__device__ float g_npsq[KK];

__device__ __forceinline__ void ldsm_x4(uint32_t&r0,uint32_t&r1,uint32_t&r2,uint32_t&r3,uint32_t saddr){
  asm volatile("ldmatrix.sync.aligned.m8n8.x4.shared.b16 {%0,%1,%2,%3}, [%4];\n"
    : "=r"(r0),"=r"(r1),"=r"(r2),"=r"(r3) : "r"(saddr));
}

__device__ __forceinline__ void mma_bf16(float c[4],
    uint32_t a0,uint32_t a1,uint32_t a2,uint32_t a3, uint32_t b0, uint32_t b1){
  asm volatile("mma.sync.aligned.m16n8k16.row.col.f32.bf16.bf16.f32 "
    "{%0,%1,%2,%3}, {%4,%5,%6,%7}, {%8,%9}, {%0,%1,%2,%3};\n"
    : "+f"(c[0]),"+f"(c[1]),"+f"(c[2]),"+f"(c[3])
    : "r"(a0),"r"(a1),"r"(a2),"r"(a3),"r"(b0),"r"(b1));
}

__device__ __forceinline__ void mbar_init(unsigned addr, unsigned cnt){
  asm volatile("mbarrier.init.shared.b64 [%0], %1;" :: "r"(addr), "r"(cnt) : "memory");
}
__device__ __forceinline__ void mbar_expect_tx(unsigned addr, unsigned bytes){
  asm volatile("mbarrier.arrive.expect_tx.shared.b64 _, [%0], %1;"
               :: "r"(addr), "r"(bytes) : "memory");
}
__device__ __forceinline__ void bulk_g2s(unsigned sdst, const void* gsrc, unsigned bytes, unsigned mbar){
  asm volatile("cp.async.bulk.shared::cta.global.mbarrier::complete_tx::bytes [%0], [%1], %2, [%3];"
               :: "r"(sdst), "l"(gsrc), "r"(bytes), "r"(mbar) : "memory");
}
__device__ __forceinline__ void mbar_wait(unsigned addr, unsigned parity){
  unsigned done;
  asm volatile("{\n\t.reg .pred p;\n\t"
    "mbarrier.try_wait.parity.acquire.cta.shared::cta.b64 p, [%1], %2;\n\t"
    "selp.b32 %0, 1, 0, p;\n\t}" : "=r"(done) : "r"(addr), "r"(parity) : "memory");
  while (!done){
    asm volatile("{\n\t.reg .pred p;\n\t"
      "mbarrier.try_wait.parity.acquire.cta.shared::cta.b64 p, [%1], %2, 0x989680;\n\t"
      "selp.b32 %0, 1, 0, p;\n\t}" : "=r"(done) : "r"(addr), "r"(parity) : "memory");
  }
}

__device__ __forceinline__ void sts64(unsigned addr, float a, float b){
  asm volatile("st.shared.v2.f32 [%0], {%1,%2};" :: "r"(addr), "f"(a), "f"(b) : "memory");
}
__device__ __forceinline__ void lds128(unsigned addr, float&a,float&b,float&c,float&d){
  asm volatile("ld.shared.v4.f32 {%0,%1,%2,%3}, [%4];" : "=f"(a),"=f"(b),"=f"(c),"=f"(d) : "r"(addr));
}

// merge 4 new values into sorted-desc top-4 (22 FMNMX, result multiset
// identical to 4 sequential single-value inserts).
__device__ __forceinline__ void merge4(float* tv, float v0, float v1, float v2, float v3){
  float s0=fmaxf(v0,v1), s1=fminf(v0,v1);
  float s2=fmaxf(v2,v3), s3=fminf(v2,v3);
  float a0=fmaxf(s0,s2), a2=fminf(s0,s2);
  float a1=fmaxf(s1,s3), a3=fminf(s1,s3);
  float b1=fmaxf(a1,a2), b2=fminf(a1,a2);   // sorted: a0 >= b1 >= b2 >= a3
  float m0=fmaxf(tv[0], a3);
  float m1=fmaxf(tv[1], b2);
  float m2=fmaxf(tv[2], b1);
  float m3=fmaxf(tv[3], a0);
  float c0=fmaxf(m0,m2), c2=fminf(m0,m2);
  float c1=fmaxf(m1,m3), c3=fminf(m1,m3);
  tv[0]=fmaxf(c0,c1); tv[1]=fminf(c0,c1);
  tv[2]=fmaxf(c2,c3); tv[3]=fminf(c2,c3);
}
// pack score value with 10-bit column index in low mantissa bits (1 LOP3)
__device__ __forceinline__ float packvi(float t, int col){
  return __uint_as_float((__float_as_uint(t) & 0xFFFFFC00u) | (unsigned)col);
}

// ---------------------------------------------------------------------------
// Kernel 1: prototypes -> padded bf16 tile image + psq/npsq.  1 warp / row.
// Image: chunk = row/128, local r = row%128, layout [r][STR] bf16.
// ---------------------------------------------------------------------------
__global__ void __launch_bounds__(128) proto_prep_kernel(const float* __restrict__ p){
  int row  = blockIdx.x*4 + (threadIdx.x>>5);
  int lane = threadIdx.x & 31;
  float4 v = reinterpret_cast<const float4*>(p + (size_t)row*DD)[lane];
  float s = v.x*v.x + v.y*v.y + v.z*v.z + v.w*v.w;
  __nv_bfloat162 b0 = __floats2bfloat162_rn(v.x, v.y);
  __nv_bfloat162 b1 = __floats2bfloat162_rn(v.z, v.w);
  uint2 w; w.x = *(uint32_t*)&b0; w.y = *(uint32_t*)&b1;
  int chunk = row >> 7, r = row & 127;
  *(uint2*)(g_pimg + (size_t)chunk*B_HALF + r*(STR*2) + lane*8) = w;
  #pragma unroll
  for (int o=16;o;o>>=1) s += __shfl_xor_sync(FULLM, s, o);
  if (!lane){ g_psq[row] = s; g_npsq[row] = -s; }
}

// ---------------------------------------------------------------------------
// Kernel 2: fused GEMM (A-in-registers, warptile 16x64) + staged coalesced
// scores stores + merge4 packed top-4 + exact fixup.
// 8 chunks of BN=128. 2-slot cp.async.bulk B ring. 2 CTAs/SM.
// ---------------------------------------------------------------------------
__global__ void __launch_bounds__(NTHREADS,2)
gemm_scores_kernel(const float* __restrict__ x, const float* __restrict__ p,
                   float* __restrict__ scores, float* __restrict__ matched)
{
  extern __shared__ char smem[];
  __nv_bfloat16* xs    = (__nv_bfloat16*)(smem + A_OFF);
  float*         npsq_s= (float*)(smem + NPSQ_OFF);
  float*         xsq_s = (float*)(smem + XSQ_OFF);

  const int tid  = threadIdx.x;
  const int lane = tid & 31;
  const int wid  = tid >> 5;
  const int wm   = wid >> 1;   // 0..3 (M)
  const int wn   = wid & 1;    // 0..1 (N)
  const int blockRow = blockIdx.x * BM;

  const unsigned smem_u32 = (unsigned)__cvta_generic_to_shared(smem);
  const unsigned xs_u32 = smem_u32 + A_OFF;
  const unsigned ps_u32 = smem_u32 + B_OFF;
  const unsigned mb_u32 = smem_u32 + MBAR_OFF;

  // init mbarriers + kick off first two bulk loads (single thread)
  if (tid == 0){
    mbar_init(mb_u32,     1);
    mbar_init(mb_u32 + 8, 1);
    mbar_expect_tx(mb_u32, B_HALF);
    bulk_g2s(ps_u32, g_pimg, B_HALF, mb_u32);
    mbar_expect_tx(mb_u32 + 8, B_HALF);
    bulk_g2s(ps_u32 + B_HALF, g_pimg + B_HALF, B_HALF, mb_u32 + 8);
  }

  // negated psq -> smem (once)
  #pragma unroll
  for (int k=0;k<4;k++) npsq_s[tid + k*NTHREADS] = g_npsq[tid + k*NTHREADS];

  // x tile fp32 -> bf16 smem + row sumsq (4 threads / row)
  {
    int r = tid >> 2;          // 0..63
    int q = tid & 3;
    const float4* src = (const float4*)(x + (size_t)(blockRow + r)*DD + q*32);
    float s = 0.f;
    #pragma unroll
    for (int i=0;i<8;i++){
      float4 v = src[i];
      s += v.x*v.x + v.y*v.y + v.z*v.z + v.w*v.w;
      __nv_bfloat162 b0 = __floats2bfloat162_rn(v.x, v.y);
      __nv_bfloat162 b1 = __floats2bfloat162_rn(v.z, v.w);
      *(__nv_bfloat162*)&xs[r*STR + q*32 + i*4]     = b0;
      *(__nv_bfloat162*)&xs[r*STR + q*32 + i*4 + 2] = b1;
    }
    s += __shfl_xor_sync(FULLM, s, 1);
    s += __shfl_xor_sync(FULLM, s, 2);
    if (!q) xsq_s[r] = s;
  }
  __syncthreads();

  // A fragments for all of K: afr[8 ksteps][4 regs] = 32 regs (16 M-rows/warp)
  uint32_t afr[8][4];
  {
    unsigned aAddr = xs_u32 + ((wm*16 + (lane&15))*STR + (lane>>4)*8)*2;
    #pragma unroll
    for (int kt=0;kt<8;kt++)
      ldsm_x4(afr[kt][0],afr[kt][1],afr[kt][2],afr[kt][3], aAddr + kt*32);
  }

  // per-thread row sumsq (2 rows per thread: h=0,1)
  float xq[2];
  #pragma unroll
  for (int h=0;h<2;h++)
    xq[h] = xsq_s[wm*16 + h*8 + (lane>>2)];

  // B ldmatrix base offset within a ring slot (nfp adds 16*STR*2 = 4352)
  const unsigned bOff = ((wn*64 + (lane>>4)*8 + (lane&7))*STR + ((lane>>3)&1)*8)*2;

  // staging addresses: h=0,1 bases; nf adds 32 bytes
  const int cl2 = (lane&3)*2;
  unsigned stsB[2];
  #pragma unroll
  for (int h=0;h<2;h++){
    int r = wm*16 + h*8 + (lane>>2);
    stsB[h] = smem_u32 + A_OFF + (unsigned)(r*SSTR + wn*64 + cl2)*4;
  }
  // store phase: warp wid streams rows wid*8 .. +8, one full row per iter
  const unsigned ldsBase = smem_u32 + A_OFF + (unsigned)(wid*8*SSTR + lane*4)*4;
  float* gBase = scores + (size_t)(blockRow + wid*8)*KK + lane*4;

  // packed top-4 per thread per row (2 rows)
  float tv[2][4];
  #pragma unroll
  for (int r=0;r<2;r++)
    #pragma unroll
    for (int j=0;j<4;j++) tv[r][j] = -1e30f;

  for (int chunk=0; chunk<NCHUNK; chunk++){
    mbar_wait(mb_u32 + (chunk&1)*8, (chunk>>1)&1);
    __syncthreads();   // slot data visible; stage free (prev chunk's reads done)

    const unsigned bBase = ps_u32 + (chunk&1)*B_HALF + bOff;

    float acc[8][4];
    #pragma unroll
    for (int nf=0;nf<8;nf++)
      #pragma unroll
      for (int q=0;q<4;q++) acc[nf][q] = 0.f;

    #pragma unroll
    for (int kt=0;kt<8;kt++){
      #pragma unroll
      for (int nfp=0;nfp<4;nfp++){
        uint32_t b[4];
        ldsm_x4(b[0],b[1],b[2],b[3], bBase + nfp*4352 + kt*32);
        mma_bf16(acc[2*nfp+0], afr[kt][0],afr[kt][1],afr[kt][2],afr[kt][3], b[0], b[1]);
        mma_bf16(acc[2*nfp+1], afr[kt][0],afr[kt][1],afr[kt][2],afr[kt][3], b[2], b[3]);
      }
    }

    // epilogue: o = (2xp - psq) - xsq -> stage; merge4 packed top-4
    const int colBase = chunk*BN + wn*64;
    float npq[16];
    #pragma unroll
    for (int nf=0;nf<8;nf++){
      float2 v = *(const float2*)&npsq_s[colBase + nf*8 + cl2];
      npq[2*nf] = v.x; npq[2*nf+1] = v.y;
    }
    #pragma unroll
    for (int h=0;h<2;h++){
      const float xqv = xq[h];
      #pragma unroll
      for (int nfp=0;nfp<4;nfp++){
        const int nf0 = 2*nfp, nf1 = 2*nfp+1;
        const int c0 = colBase + nf0*8 + cl2;
        const int c1 = colBase + nf1*8 + cl2;
        float o00 = fmaf(2.f, acc[nf0][h*2+0], npq[2*nf0+0]) - xqv;
        float o01 = fmaf(2.f, acc[nf0][h*2+1], npq[2*nf0+1]) - xqv;
        float o10 = fmaf(2.f, acc[nf1][h*2+0], npq[2*nf1+0]) - xqv;
        float o11 = fmaf(2.f, acc[nf1][h*2+1], npq[2*nf1+1]) - xqv;
        sts64(stsB[h] + nf0*32, o00, o01);
        sts64(stsB[h] + nf1*32, o10, o11);
        merge4(tv[h], packvi(o00,c0), packvi(o01,c0+1),
                       packvi(o10,c1), packvi(o11,c1+1));
      }
    }
    __syncthreads();   // stage complete; all slot reads done

    // refill the just-freed slot with chunk+2
    if (chunk+2 < NCHUNK && tid == 0){
      unsigned mb = mb_u32 + (chunk&1)*8;
      mbar_expect_tx(mb, B_HALF);
      bulk_g2s(ps_u32 + (chunk&1)*B_HALF, g_pimg + (size_t)(chunk+2)*B_HALF, B_HALF, mb);
    }

    // coalesced store phase: warp streams 8 rows x 512B
    float* gp = gBase + chunk*BN;
    #pragma unroll
    for (int j=0;j<8;j++){
      float a,b,c,d;
      lds128(ldsBase + (unsigned)(j*SSTR)*4, a,b,c,d);
      float4 v; v.x=a; v.y=b; v.z=c; v.w=d;
      *(float4*)(gp + (size_t)j*KK) = v;
    }
  }
  __syncthreads();

  // ---- per-row candidate merge (32 packed cands/row -> top 4) ----
  float* mv = (float*)(smem + A_OFF);              // [64][32] = 8KB
  int4*  c4 = (int4*) (smem + A_OFF + 64*32*4);    // [64]
  #pragma unroll
  for (int h=0;h<2;h++){
    int r = wm*16 + h*8 + (lane>>2);
    int base = r*32 + wn*16 + (lane&3)*4;
    #pragma unroll
    for (int j=0;j<4;j++) mv[base+j] = tv[h][j];
  }
  __syncthreads();
  if (tid < BM){
    float bv[4] = {-1e30f,-1e30f,-1e30f,-1e30f};
    #pragma unroll
    for (int s=0;s<8;s++)
      merge4(bv, mv[tid*32+s*4], mv[tid*32+s*4+1], mv[tid*32+s*4+2], mv[tid*32+s*4+3]);
    int4 o;
    o.x = (int)(__float_as_uint(bv[0]) & 1023u);
    o.y = (int)(__float_as_uint(bv[1]) & 1023u);
    o.z = (int)(__float_as_uint(bv[2]) & 1023u);
    o.w = (int)(__float_as_uint(bv[3]) & 1023u);
    c4[tid] = o;
  }
  __syncthreads();

  // ---- exact fp32 fixup: 8 warps x 8 rows, 4 candidates each ----
  #pragma unroll
  for (int rr=0; rr<8; rr++){
    const int r    = wid*8 + rr;
    const int grow = blockRow + r;
    float4 xv = reinterpret_cast<const float4*>(x + (size_t)grow*DD)[lane];
    const float xqe = xsq_s[r];
    int4 cd = c4[r];
    int cands[4] = {cd.x, cd.y, cd.z, cd.w};
    float bt = 1e30f; int bi = 0x7fffffff;
    #pragma unroll
    for (int j=0;j<4;j++){
      int ci = cands[j];
      float4 pv = reinterpret_cast<const float4*>(p + (size_t)ci*DD)[lane];
      float d = xv.x*pv.x + xv.y*pv.y + xv.z*pv.z + xv.w*pv.w;
      #pragma unroll
      for (int o=16;o;o>>=1) d += __shfl_xor_sync(FULLM, d, o);
      float t = (xqe + g_psq[ci]) - 2.f*d;   // minimize
      if (t < bt || (t == bt && ci < bi)){ bt = t; bi = ci; }
    }
    float4 pv = reinterpret_cast<const float4*>(p + (size_t)bi*DD)[lane];
    reinterpret_cast<float4*>(matched + (size_t)grow*DD)[lane] = pv;
  }
}

// ---------------------------------------------------------------------------
extern "C" void kernel_launch(void* const* d_in, const int* in_sizes, int n_in,
                              void* d_out, int out_size)
{
  const float* x = (const float*)d_in[0];   // [8,4096,128] f32
  const float* p = (const float*)d_in[1];   // [1024,128]   f32
  float* matched = (float*)d_out;                                  // [32768,128]
  float* scores  = (float*)d_out + (size_t)M_TOTAL*DD;             // [32768,1024]

  cudaFuncSetAttribute(gemm_scores_kernel,
                       cudaFuncAttributeMaxDynamicSharedMemorySize, SMEM_BYTES);

  proto_prep_kernel<<<KK/4, 128>>>(p);
  gemm_scores_kernel<<<M_TOTAL/BM, NTHREADS, SMEM_BYTES>>>(x, p, scores, matched);
}

// round 16
// speedup vs baseline: 1.2587x; 1.2587x over previous
#include <cuda_runtime.h>
#include <cuda_bf16.h>
#include <cstdint>

#define FULLM 0xFFFFFFFFu

// Problem dims
#define DD 128
#define KK 1024
#define M_TOTAL 32768

// GEMM tiling
#define BM 64
#define BN 64
#define STR 136            // padded bf16 row stride (272B)
#define NCHUNK (KK/BN)     // 16
#define NTHREADS 256       // 8 warps: 2 (M) x 4 (N), warptile 32x16

// smem layout (bytes)
#define A_OFF    0
#define A_BYTES  (BM*STR*2)             // 17408
#define B_OFF    A_BYTES                // ring of 3
#define B_HALF   (BN*STR*2)             // 17408
#define NPSQ_OFF (B_OFF + 3*B_HALF)     // 69632
#define XSQ_OFF  (NPSQ_OFF + 4096)      // 73728
#define MBAR_OFF (XSQ_OFF + 256)        // 73984: full[0..2], free[0..2]
#define SMEM_BYTES (MBAR_OFF + 96)      // 74080 (x2 CTAs fits 227KB)

// device scratch: P tiles pre-laid-out as padded [64][STR] bf16 smem images
__device__ __align__(16) unsigned char g_pimg[NCHUNK*B_HALF];
__device__ float g_psq[KK];
__device__ float g_npsq[KK];

__device__ __forceinline__ void ldsm_x4(uint32_t&r0,uint32_t&r1,uint32_t&r2,uint32_t&r3,uint32_t saddr){
  asm volatile("ldmatrix.sync.aligned.m8n8.x4.shared.b16 {%0,%1,%2,%3}, [%4];\n"
    : "=r"(r0),"=r"(r1),"=r"(r2),"=r"(r3) : "r"(saddr));
}

__device__ __forceinline__ void mma_bf16(float c[4],
    uint32_t a0,uint32_t a1,uint32_t a2,uint32_t a3, uint32_t b0, uint32_t b1){
  asm volatile("mma.sync.aligned.m16n8k16.row.col.f32.bf16.bf16.f32 "
    "{%0,%1,%2,%3}, {%4,%5,%6,%7}, {%8,%9}, {%0,%1,%2,%3};\n"
    : "+f"(c[0]),"+f"(c[1]),"+f"(c[2]),"+f"(c[3])
    : "r"(a0),"r"(a1),"r"(a2),"r"(a3),"r"(b0),"r"(b1));
}

__device__ __forceinline__ void mbar_init(unsigned addr, unsigned cnt){
  asm volatile("mbarrier.init.shared.b64 [%0], %1;" :: "r"(addr), "r"(cnt) : "memory");
}
__device__ __forceinline__ void mbar_expect_tx(unsigned addr, unsigned bytes){
  asm volatile("mbarrier.arrive.expect_tx.shared.b64 _, [%0], %1;"
               :: "r"(addr), "r"(bytes) : "memory");
}
__device__ __forceinline__ void mbar_arrive(unsigned addr){
  asm volatile("mbarrier.arrive.shared.b64 _, [%0];" :: "r"(addr) : "memory");
}
__device__ __forceinline__ void bulk_g2s(unsigned sdst, const void* gsrc, unsigned bytes, unsigned mbar){
  asm volatile("cp.async.bulk.shared::cta.global.mbarrier::complete_tx::bytes [%0], [%1], %2, [%3];"
               :: "r"(sdst), "l"(gsrc), "r"(bytes), "r"(mbar) : "memory");
}
__device__ __forceinline__ void mbar_wait(unsigned addr, unsigned parity){
  unsigned done;
  asm volatile("{\n\t.reg .pred p;\n\t"
    "mbarrier.try_wait.parity.acquire.cta.shared::cta.b64 p, [%1], %2;\n\t"
    "selp.b32 %0, 1, 0, p;\n\t}" : "=r"(done) : "r"(addr), "r"(parity) : "memory");
  while (!done){
    asm volatile("{\n\t.reg .pred p;\n\t"
      "mbarrier.try_wait.parity.acquire.cta.shared::cta.b64 p, [%1], %2, 0x989680;\n\t"
      "selp.b32 %0, 1, 0, p;\n\t}" : "=r"(done) : "r"(addr), "r"(parity) : "memory");
  }
}

// merge 4 new values into sorted-desc top-4 (22 FMNMX, result multiset
// identical to 4 sequential single-value inserts).
__device__ __forceinline__ void merge4(float* tv, float v0, float v1, float v2, float v3){
  float s0=fmaxf(v0,v1), s1=fminf(v0,v1);
  float s2=fmaxf(v2,v3), s3=fminf(v2,v3);
  float a0=fmaxf(s0,s2), a2=fminf(s0,s2);
  float a1=fmaxf(s1,s3), a3=fminf(s1,s3);
  float b1=fmaxf(a1,a2), b2=fminf(a1,a2);   // sorted: a0 >= b1 >= b2 >= a3
  float m0=fmaxf(tv[0], a3);
  float m1=fmaxf(tv[1], b2);
  float m2=fmaxf(tv[2], b1);
  float m3=fmaxf(tv[3], a0);
  float c0=fmaxf(m0,m2), c2=fminf(m0,m2);
  float c1=fmaxf(m1,m3), c3=fminf(m1,m3);
  tv[0]=fmaxf(c0,c1); tv[1]=fminf(c0,c1);
  tv[2]=fmaxf(c2,c3); tv[3]=fminf(c2,c3);
}
// pack score value with 10-bit column index in low mantissa bits (1 LOP3)
__device__ __forceinline__ float packvi(float t, int col){
  return __uint_as_float((__float_as_uint(t) & 0xFFFFFC00u) | (unsigned)col);
}

// ---------------------------------------------------------------------------
// Kernel 1: prototypes -> padded bf16 tile image + psq/npsq.  1 warp / row.
// ---------------------------------------------------------------------------
__global__ void __launch_bounds__(128) proto_prep_kernel(const float* __restrict__ p){
  int row  = blockIdx.x*4 + (threadIdx.x>>5);
  int lane = threadIdx.x & 31;
  float4 v = reinterpret_cast<const float4*>(p + (size_t)row*DD)[lane];
  float s = v.x*v.x + v.y*v.y + v.z*v.z + v.w*v.w;
  __nv_bfloat162 b0 = __floats2bfloat162_rn(v.x, v.y);
  __nv_bfloat162 b1 = __floats2bfloat162_rn(v.z, v.w);
  uint2 w; w.x = *(uint32_t*)&b0; w.y = *(uint32_t*)&b1;
  int chunk = row >> 6, r = row & 63;
  *(uint2*)(g_pimg + (size_t)chunk*B_HALF + r*(STR*2) + lane*8) = w;
  #pragma unroll
  for (int o=16;o;o>>=1) s += __shfl_xor_sync(FULLM, s, o);
  if (!lane){ g_psq[row] = s; g_npsq[row] = -s; }
}

// ---------------------------------------------------------------------------
// Kernel 2: fused GEMM (A-in-registers) + direct scores stores + merge4
// packed top-4 + exact fixup.  Warp-autonomous pipeline: NO __syncthreads
// in the chunk loop — full[s] (tx) / free[s] (count=8) mbarrier protocol,
// warp 0 refills slots.  3-slot bulk ring, 2 CTAs/SM.
// ---------------------------------------------------------------------------
__global__ void __launch_bounds__(NTHREADS,2)
gemm_scores_kernel(const float* __restrict__ x, const float* __restrict__ p,
                   float* __restrict__ scores, float* __restrict__ matched)
{
  extern __shared__ char smem[];
  __nv_bfloat16* xs    = (__nv_bfloat16*)(smem + A_OFF);
  float*         npsq_s= (float*)(smem + NPSQ_OFF);
  float*         xsq_s = (float*)(smem + XSQ_OFF);

  const int tid  = threadIdx.x;
  const int lane = tid & 31;
  const int wid  = tid >> 5;
  const int wm   = wid >> 2;   // 0..1
  const int wn   = wid & 3;    // 0..3
  const int blockRow = blockIdx.x * BM;

  const unsigned smem_u32 = (unsigned)__cvta_generic_to_shared(smem);
  const unsigned xs_u32 = smem_u32 + A_OFF;
  const unsigned ps_u32 = smem_u32 + B_OFF;
  const unsigned mbF_u32 = smem_u32 + MBAR_OFF;        // full[0..2]
  const unsigned mbE_u32 = smem_u32 + MBAR_OFF + 24;   // free[0..2]

  // init mbarriers + kick off first three bulk loads (single thread)
  if (tid == 0){
    #pragma unroll
    for (int s=0;s<3;s++){
      mbar_init(mbF_u32 + s*8, 1);
      mbar_init(mbE_u32 + s*8, 8);
    }
    #pragma unroll
    for (int c=0;c<3;c++){
      mbar_expect_tx(mbF_u32 + c*8, B_HALF);
      bulk_g2s(ps_u32 + c*B_HALF, g_pimg + (size_t)c*B_HALF, B_HALF, mbF_u32 + c*8);
    }
  }

  // negated psq -> smem (once)
  #pragma unroll
  for (int k=0;k<4;k++) npsq_s[tid + k*NTHREADS] = g_npsq[tid + k*NTHREADS];

  // x tile fp32 -> bf16 smem + row sumsq (4 threads / row)
  {
    int r = tid >> 2;          // 0..63
    int q = tid & 3;
    const float4* src = (const float4*)(x + (size_t)(blockRow + r)*DD + q*32);
    float s = 0.f;
    #pragma unroll
    for (int i=0;i<8;i++){
      float4 v = src[i];
      s += v.x*v.x + v.y*v.y + v.z*v.z + v.w*v.w;
      __nv_bfloat162 b0 = __floats2bfloat162_rn(v.x, v.y);
      __nv_bfloat162 b1 = __floats2bfloat162_rn(v.z, v.w);
      *(__nv_bfloat162*)&xs[r*STR + q*32 + i*4]     = b0;
      *(__nv_bfloat162*)&xs[r*STR + q*32 + i*4 + 2] = b1;
    }
    s += __shfl_xor_sync(FULLM, s, 1);
    s += __shfl_xor_sync(FULLM, s, 2);
    if (!q) xsq_s[r] = s;
  }
  __syncthreads();   // A tile + npsq + mbarriers visible to all warps

  // A fragments for all of K: a[8 ksteps][2 mf][4 regs] = 64 regs, loaded once.
  uint32_t afr[8][2][4];
  {
    unsigned aAddr[2];
    #pragma unroll
    for (int mf=0;mf<2;mf++)
      aAddr[mf] = xs_u32 + ((wm*32 + mf*16 + (lane&15))*STR + (lane>>4)*8)*2;
    #pragma unroll
    for (int kt=0;kt<8;kt++)
      #pragma unroll
      for (int mf=0;mf<2;mf++)
        ldsm_x4(afr[kt][mf][0],afr[kt][mf][1],afr[kt][mf][2],afr[kt][mf][3],
                aAddr[mf] + kt*32);
  }

  // per-thread row sumsq (4 rows per thread: mf2 x h2)
  float xq[4];
  #pragma unroll
  for (int mf=0;mf<2;mf++)
    #pragma unroll
    for (int h=0;h<2;h++)
      xq[mf*2+h] = xsq_s[wm*32 + mf*16 + h*8 + (lane>>2)];

  // B ldmatrix offset within a ring slot
  const unsigned bOff = ((wn*16 + (lane>>4)*8 + (lane&7))*STR + ((lane>>3)&1)*8)*2;

  // packed top-4 per thread per row
  float tv[4][4];
  #pragma unroll
  for (int r=0;r<4;r++)
    #pragma unroll
    for (int j=0;j<4;j++) tv[r][j] = -1e30f;

  int slot = 0;
  int parity = 0;
  for (int chunk=0; chunk<NCHUNK; chunk++){
    // wait for this slot's data (per-warp; no CTA barrier)
    mbar_wait(mbF_u32 + slot*8, parity);

    const unsigned bBase = ps_u32 + slot*B_HALF + bOff;

    float acc[2][2][4];
    #pragma unroll
    for (int mf=0;mf<2;mf++)
      #pragma unroll
      for (int nf=0;nf<2;nf++)
        #pragma unroll
        for (int q=0;q<4;q++) acc[mf][nf][q] = 0.f;

    #pragma unroll
    for (int kt=0;kt<8;kt++){
      uint32_t b[4];
      ldsm_x4(b[0],b[1],b[2],b[3], bBase + kt*32);
      #pragma unroll
      for (int mf=0;mf<2;mf++){
        mma_bf16(acc[mf][0], afr[kt][mf][0],afr[kt][mf][1],afr[kt][mf][2],afr[kt][mf][3], b[0], b[1]);
        mma_bf16(acc[mf][1], afr[kt][mf][0],afr[kt][mf][1],afr[kt][mf][2],afr[kt][mf][3], b[2], b[3]);
      }
    }

    // this warp is done reading the slot
    if (lane == 0) mbar_arrive(mbE_u32 + slot*8);

    // warp 0: refill this slot with chunk+3 once ALL warps have arrived
    if (wid == 0 && chunk+3 < NCHUNK){
      mbar_wait(mbE_u32 + slot*8, parity);
      if (lane == 0){
        mbar_expect_tx(mbF_u32 + slot*8, B_HALF);
        bulk_g2s(ps_u32 + slot*B_HALF, g_pimg + (size_t)(chunk+3)*B_HALF,
                 B_HALF, mbF_u32 + slot*8);
      }
    }

    // epilogue: scores = (2xp - psq) - xsq (direct stores); merge4 top-4
    const int colBase = chunk*BN + wn*16;
    const int cl2 = (lane&3)*2;
    float npq[4];
    {
      float2 v0 = *(const float2*)&npsq_s[colBase + cl2];
      float2 v1 = *(const float2*)&npsq_s[colBase + 8 + cl2];
      npq[0]=v0.x; npq[1]=v0.y; npq[2]=v1.x; npq[3]=v1.y;
    }
    #pragma unroll
    for (int mf=0;mf<2;mf++){
      #pragma unroll
      for (int h=0;h<2;h++){
        const int rl   = mf*2 + h;
        const int grow = blockRow + wm*32 + mf*16 + h*8 + (lane>>2);
        const float xqv = xq[rl];
        float* srow = scores + (size_t)grow*KK;
        const int c0 = colBase + cl2;
        const int c1 = colBase + 8 + cl2;
        float t00 = fmaf(2.f, acc[mf][0][h*2+0], npq[0]);
        float t01 = fmaf(2.f, acc[mf][0][h*2+1], npq[1]);
        float t10 = fmaf(2.f, acc[mf][1][h*2+0], npq[2]);
        float t11 = fmaf(2.f, acc[mf][1][h*2+1], npq[3]);
        float2 o0; o0.x = t00 - xqv; o0.y = t01 - xqv;
        float2 o1; o1.x = t10 - xqv; o1.y = t11 - xqv;
        *(float2*)(srow + c0) = o0;
        *(float2*)(srow + c1) = o1;
        merge4(tv[rl], packvi(t00 - xqv, c0), packvi(t01 - xqv, c0+1),
                        packvi(t10 - xqv, c1), packvi(t11 - xqv, c1+1));
      }
    }

    slot++; if (slot >= 3){ slot = 0; parity ^= 1; }
  }
  __syncthreads();   // all warps done with loop before reusing A region

  // ---- per-row candidate merge (64 packed cands/row -> top 4) ----
  float* mv = (float*)(smem + A_OFF);              // [64][64] = 16KB
  int4*  c4 = (int4*) (smem + A_OFF + 64*64*4);    // [64]
  #pragma unroll
  for (int mf=0;mf<2;mf++){
    #pragma unroll
    for (int h=0;h<2;h++){
      int r = wm*32 + mf*16 + h*8 + (lane>>2);
      int base = r*64 + wn*16 + (lane&3)*4;
      #pragma unroll
      for (int j=0;j<4;j++) mv[base+j] = tv[mf*2+h][j];
    }
  }
  __syncthreads();
  if (tid < BM){
    float bv[4] = {-1e30f,-1e30f,-1e30f,-1e30f};
    #pragma unroll
    for (int s=0;s<16;s++)
      merge4(bv, mv[tid*64+s*4], mv[tid*64+s*4+1], mv[tid*64+s*4+2], mv[tid*64+s*4+3]);
    int4 o;
    o.x = (int)(__float_as_uint(bv[0]) & 1023u);
    o.y = (int)(__float_as_uint(bv[1]) & 1023u);
    o.z = (int)(__float_as_uint(bv[2]) & 1023u);
    o.w = (int)(__float_as_uint(bv[3]) & 1023u);
    c4[tid] = o;
  }
  __syncthreads();

  // ---- exact fp32 fixup: 8 warps x 8 rows, 4 candidates each ----
  #pragma unroll
  for (int rr=0; rr<8; rr++){
    const int r    = wid*8 + rr;
    const int grow = blockRow + r;
    float4 xv = reinterpret_cast<const float4*>(x + (size_t)grow*DD)[lane];
    const float xqe = xsq_s[r];
    int4 cd = c4[r];
    int cands[4] = {cd.x, cd.y, cd.z, cd.w};
    float bt = 1e30f; int bi = 0x7fffffff;
    #pragma unroll
    for (int j=0;j<4;j++){
      int ci = cands[j];
      float4 pv = reinterpret_cast<const float4*>(p + (size_t)ci*DD)[lane];
      float d = xv.x*pv.x + xv.y*pv.y + xv.z*pv.z + xv.w*pv.w;
      #pragma unroll
      for (int o=16;o;o>>=1) d += __shfl_xor_sync(FULLM, d, o);
      float t = (xqe + g_psq[ci]) - 2.f*d;   // minimize
      if (t < bt || (t == bt && ci < bi)){ bt = t; bi = ci; }
    }
    float4 pv = reinterpret_cast<const float4*>(p + (size_t)bi*DD)[lane];
    reinterpret_cast<float4*>(matched + (size_t)grow*DD)[lane] = pv;
  }
}

// ---------------------------------------------------------------------------
extern "C" void kernel_launch(void* const* d_in, const int* in_sizes, int n_in,
                              void* d_out, int out_size)
{
  const float* x = (const float*)d_in[0];   // [8,4096,128] f32
  const float* p = (const float*)d_in[1];   // [1024,128]   f32
  float* matched = (float*)d_out;                                  // [32768,128]
  float* scores  = (float*)d_out + (size_t)M_TOTAL*DD;             // [32768,1024]

  cudaFuncSetAttribute(gemm_scores_kernel,
                       cudaFuncAttributeMaxDynamicSharedMemorySize, SMEM_BYTES);

  proto_prep_kernel<<<KK/4, 128>>>(p);
  gemm_scores_kernel<<<M_TOTAL/BM, NTHREADS, SMEM_BYTES>>>(x, p, scores, matched);
}